// round 7
// baseline (speedup 1.0000x reference)
#include <cuda_runtime.h>
#include <cuda_fp16.h>
#include <stdint.h>

#define RES 512
#define PR  514           // padded resolution: 1-texel zero ring
#define CH  32
#define PLANE_PAD_ELEMS (PR * PR * CH)

// Zero-padded (H, W, C) fp16 planes. Texel = 32 halves = 64B.
// Interior texel (y, x) lives at padded coords (y+1, x+1).
// padding_mode='zeros' is realized physically -> no border logic in sampler.
__device__ __align__(128) __half g_TP[3][PLANE_PAD_ELEMS];

// ---------------------------------------------------------------------------
// Zero the border ring (2052 texels per plane).
// ---------------------------------------------------------------------------
__global__ __launch_bounds__(256) void border_zero_kernel()
{
    const int t = blockIdx.x * blockDim.x + threadIdx.x;
    if (t >= 3 * 2052) return;
    const int p = t / 2052;
    const int b = t % 2052;
    int y, x;
    if (b < 514)       { y = 0;   x = b; }
    else if (b < 1028) { y = 513; x = b - 514; }
    else {
        const int i = b - 1028;
        if (i < 512) { y = i + 1; x = 0; }
        else         { y = i - 512 + 1; x = 513; }
    }
    uint4* d = (uint4*)(g_TP[p] + ((size_t)y * PR + x) * CH);
    d[0] = d[1] = d[2] = d[3] = make_uint4(0u, 0u, 0u, 0u);
}

// ---------------------------------------------------------------------------
// Transpose (C, H, W) fp32 -> padded (H, W, C) fp16 via shared 32x32 tile.
// grid = (RES, RES/32, 3), block = (32, 8).
// ---------------------------------------------------------------------------
__global__ __launch_bounds__(256) void triplane_transpose_kernel(
    const float* __restrict__ t_xy,
    const float* __restrict__ t_yz,
    const float* __restrict__ t_zx)
{
    __shared__ float tile[32][33];   // [channel][x-in-tile]

    const int y  = blockIdx.x;
    const int x0 = blockIdx.y * 32;
    const int p  = blockIdx.z;
    const int tx = threadIdx.x;      // 0..31
    const int ty = threadIdx.y;      // 0..7

    const float* src = (p == 0) ? t_xy : (p == 1) ? t_yz : t_zx;
    const float* s = src + y * RES + x0 + tx;

#pragma unroll
    for (int i = 0; i < 4; ++i) {
        const int c = ty + 8 * i;
        tile[c][tx] = s[c * (RES * RES)];   // coalesced, MLP=4
    }
    __syncthreads();

    const int tid = ty * 32 + tx;
    if (tid < 128) {
        const int xx  = tid >> 2;        // texel within tile (0..31)
        const int seg = tid & 3;         // 16B segment of the 64B texel

        uint4 v;
#pragma unroll
        for (int j = 0; j < 4; ++j) {
            const int c = seg * 8 + 2 * j;
            ((__half2*)&v)[j] = __floats2half2_rn(tile[c][xx], tile[c + 1][xx]);
        }
        // padded destination: (y+1, x+1)
        *(uint4*)(g_TP[p] + ((size_t)(y + 1) * PR + (x0 + xx + 1)) * CH + seg * 8) = v;
    }
}

// ---------------------------------------------------------------------------
// Packed f32x2 helpers (FFMA2 is PTX-only; ptxas won't auto-fuse).
// ---------------------------------------------------------------------------
__device__ __forceinline__ unsigned long long pack2(float lo, float hi)
{
    unsigned long long r;
    asm("mov.b64 %0, {%1, %2};" : "=l"(r) : "f"(lo), "f"(hi));
    return r;
}
__device__ __forceinline__ void ffma2(unsigned long long& d,
                                      unsigned long long a,
                                      unsigned long long b)
{
    asm("fma.rn.f32x2 %0, %1, %2, %0;" : "+l"(d) : "l"(a), "l"(b));
}
__device__ __forceinline__ float2 unpack2(unsigned long long v)
{
    float2 f;
    asm("mov.b64 {%0, %1}, %2;" : "=f"(f.x), "=f"(f.y) : "l"(v));
    return f;
}

// ---------------------------------------------------------------------------
// Sampling: 8 lanes per point (xsel = lane>>2 picks x corner, chunk = lane&3
// picks 8 channels). One warp instruction per (plane,row) covers both x
// corners as a contiguous 128B span. No border branches (physical zero ring).
// ---------------------------------------------------------------------------
__global__ __launch_bounds__(256) void triplane_sample_kernel(
    const float* __restrict__ xyz,
    float* __restrict__ out,
    int npts)
{
    const int gtid  = blockIdx.x * blockDim.x + threadIdx.x;
    const int pid   = gtid >> 3;
    const int s     = gtid & 7;
    const int chunk = s & 3;
    const int xsel  = s >> 2;
    if (pid >= npts) return;

    const float cx = __ldg(xyz + pid * 3 + 0);
    const float cy = __ldg(xyz + pid * 3 + 1);
    const float cz = __ldg(xyz + pid * 3 + 2);

    // f_xy: (X, Y)   f_yz: (Y, Z)   f_zx: (Z, X)
    const float cA[3] = {cx, cy, cz};   // W coordinate
    const float cB[3] = {cy, cz, cx};   // H coordinate

    unsigned long long acc[4];
#pragma unroll
    for (int j = 0; j < 4; ++j) acc[j] = 0ull;

    const int laneoff = chunk * 8;      // this lane's 8-channel offset (halves)

#pragma unroll
    for (int p = 0; p < 3; ++p) {
        // padded pixel coord = 256*c + 255.5 + 1; c in [-1,1) -> value in
        // [0.5, 512.5) -> trunc == floor, indices in [0,512], no clamps.
        const float xf = fmaf(cA[p], 256.0f, 256.5f);
        const float yf = fmaf(cB[p], 256.0f, 256.5f);

        const int ixp0 = (int)xf;       // trunc
        const int iyp  = (int)yf;
        const float wx1 = xf - (float)ixp0;
        const float wy1 = yf - (float)iyp;
        const float wx0 = 1.0f - wx1;
        const float wy0 = 1.0f - wy1;

        const float wxl = xsel ? wx1 : wx0;
        const float w0  = wy0 * wxl;
        const float w1  = wy1 * wxl;
        const unsigned long long w0p = pack2(w0, w0);
        const unsigned long long w1p = pack2(w1, w1);

        const __half* t = g_TP[p] + (size_t)(iyp * PR + ixp0 + xsel) * CH + laneoff;
        const uint4 v0 = __ldg((const uint4*)t);
        const uint4 v1 = __ldg((const uint4*)(t + PR * CH));

        const __half2* h0 = (const __half2*)&v0;
        const __half2* h1 = (const __half2*)&v1;
#pragma unroll
        for (int j = 0; j < 4; ++j) {
            const float2 f0 = __half22float2(h0[j]);
            const float2 f1 = __half22float2(h1[j]);
            ffma2(acc[j], pack2(f0.x, f0.y), w0p);
            ffma2(acc[j], pack2(f1.x, f1.y), w1p);
        }
    }

    // Combine the two x-corner partial sums (lane s <-> lane s^4, same chunk).
    float r[8];
#pragma unroll
    for (int j = 0; j < 4; ++j) {
        const float2 f = unpack2(acc[j]);
        r[2 * j]     = f.x;
        r[2 * j + 1] = f.y;
    }
#pragma unroll
    for (int k = 0; k < 8; ++k)
        r[k] += __shfl_xor_sync(0xffffffffu, r[k], 4);

    // xsel=0 stores floats 0-3 of the chunk, xsel=1 stores floats 4-7.
    const float4 o = xsel ? make_float4(r[4], r[5], r[6], r[7])
                          : make_float4(r[0], r[1], r[2], r[3]);
    *(float4*)(out + pid * CH + chunk * 8 + xsel * 4) = o;
}

// ---------------------------------------------------------------------------
// kernel_launch
// inputs: xyz [N*3], T_xy, T_yz, T_zx [1*32*512*512] fp32 ; output [N*32] fp32
// ---------------------------------------------------------------------------
extern "C" void kernel_launch(void* const* d_in, const int* in_sizes, int n_in,
                              void* d_out, int out_size)
{
    const float* xyz  = (const float*)d_in[0];
    const float* t_xy = (const float*)d_in[1];
    const float* t_yz = (const float*)d_in[2];
    const float* t_zx = (const float*)d_in[3];
    float* out = (float*)d_out;

    const int npts = in_sizes[0] / 3;

    // 1) zero the padding ring (disjoint from transpose writes)
    border_zero_kernel<<<(3 * 2052 + 255) / 256, 256>>>();

    // 2) transpose + fp32->fp16 into padded layout
    dim3 tgrid(RES, RES / 32, 3);
    dim3 tblock(32, 8);
    triplane_transpose_kernel<<<tgrid, tblock>>>(t_xy, t_yz, t_zx);

    // 3) sample: 8 threads per point
    const long long total = (long long)npts * 8;
    const int block = 256;
    const int grid = (int)((total + block - 1) / block);
    triplane_sample_kernel<<<grid, block>>>(xyz, out, npts);
}